// round 6
// baseline (speedup 1.0000x reference)
#include <cuda_runtime.h>
#include <cuda_bf16.h>
#include <math.h>

// ---------------- problem constants ----------------
#define BSZ   8
#define NSEQ  1024
#define DM    256
#define HH    8
#define INNER 2048          // H * DH, DH == DM (module quirk)
#define MMLP  1024
#define LNUM  4
#define ROWS  (BSZ * NSEQ)  // 8192
#define QKVC  (3 * INNER)   // 6144

#define KC  16              // K-chunk per pipeline stage (one m16n8k16 k-step)
#define KS  (KC + 2)        // padded smem row (18*2B = 36B row stride, 4B-aligned)

// ---------------- scratch (static device globals; no allocs allowed) -------
__device__ float g_x[ROWS * DM];                         // residual stream
__device__ float g_h[ROWS * DM];                         // LN output
__device__ float g_qkv[ROWS * QKVC];                     // 192 MB
__device__ float g_scores[(long)BSZ * HH * NSEQ * NSEQ]; // 256 MB
__device__ float g_attnout[ROWS * INNER];                // 64 MB
__device__ float g_h1[ROWS * MMLP];                      // 32 MB

// ---------------- copy in/out ----------------
__global__ void copy_in_kernel(const float* __restrict__ src) {
    int i = blockIdx.x * 256 + threadIdx.x;
    g_x[i] = src[i];
}
__global__ void copy_out_kernel(float* __restrict__ dst) {
    int i = blockIdx.x * 256 + threadIdx.x;
    dst[i] = g_x[i];
}

// ---------------- layernorm: one 256-thread block per row (D=256) ----------
__global__ void ln_kernel(const float* __restrict__ x,
                          const float* __restrict__ g,
                          const float* __restrict__ b,
                          float* __restrict__ out) {
    int row = blockIdx.x;
    int t = threadIdx.x;
    float v = x[row * DM + t];
    __shared__ float sh[8];

    float s = v;
    #pragma unroll
    for (int o = 16; o; o >>= 1) s += __shfl_xor_sync(0xffffffffu, s, o);
    if ((t & 31) == 0) sh[t >> 5] = s;
    __syncthreads();
    if (t == 0) {
        float z = 0.f;
        #pragma unroll
        for (int i = 0; i < 8; i++) z += sh[i];
        sh[0] = z;
    }
    __syncthreads();
    float mean = sh[0] * (1.f / 256.f);
    __syncthreads();

    float d = v - mean;
    float sq = d * d;
    #pragma unroll
    for (int o = 16; o; o >>= 1) sq += __shfl_xor_sync(0xffffffffu, sq, o);
    if ((t & 31) == 0) sh[t >> 5] = sq;
    __syncthreads();
    if (t == 0) {
        float z = 0.f;
        #pragma unroll
        for (int i = 0; i < 8; i++) z += sh[i];
        sh[0] = z;
    }
    __syncthreads();
    float var = sh[0] * (1.f / 256.f);
    float r = rsqrtf(var + 1e-5f);
    out[row * DM + t] = d * r * g[t] + b[t];
}

// ---------------- tensor-core building blocks ----------------
__device__ __forceinline__ void mma16816(float d[4], const unsigned a[4],
                                         const unsigned b[2]) {
    asm volatile(
        "mma.sync.aligned.m16n8k16.row.col.f32.bf16.bf16.f32 "
        "{%0,%1,%2,%3}, {%4,%5,%6,%7}, {%8,%9}, {%0,%1,%2,%3};\n"
        : "+f"(d[0]), "+f"(d[1]), "+f"(d[2]), "+f"(d[3])
        : "r"(a[0]), "r"(a[1]), "r"(a[2]), "r"(a[3]), "r"(b[0]), "r"(b[1]));
}

__device__ __forceinline__ void split_bf16(float v, __nv_bfloat16& hi,
                                           __nv_bfloat16& lo) {
    hi = __float2bfloat16(v);
    lo = __float2bfloat16(v - __bfloat162float(hi));
}

// ======================================================================
// Tensor-core split-bf16 GEMM core.
// Output tile 128x128 per CTA, 256 threads = 8 warps (4 along M x 2 along N).
// Each warp: 32x64 = 2x8 grid of m16n8k16 MMAs, fp32 accumulators.
// D = Ahi*Bhi + Ahi*Blo + Alo*Bhi   (fp32 accumulate, lo*lo dropped)
// BNT = 0: B is [K][N] row-major (NN).  BNT = 1: B is [N][K] row-major (NT).
// EPI 0: C = acc
// EPI 1: C = acc * 2^-4          (QK^T scale 1/sqrt(256))
// EPI 2: C = C + acc + bias[col] (residual accumulate, in-place)
// EPI 3: C = gelu_erf(acc + bias[col])
// ======================================================================
template <int EPI, int BNT>
__device__ __forceinline__ void gemm_core(
    const float* __restrict__ A, const float* __restrict__ B,
    float* __restrict__ C, int K, int lda, int ldb, int ldc,
    const float* __restrict__ bias) {
    __shared__ __nv_bfloat16 sAhi[2][128][KS], sAlo[2][128][KS];
    __shared__ __nv_bfloat16 sBhi[2][128][KS], sBlo[2][128][KS];

    const int bm = blockIdx.y * 128, bn = blockIdx.x * 128;
    const int tid = threadIdx.x;
    const int lane = tid & 31, wid = tid >> 5;
    const int wm = (wid & 3) * 32;   // warp row offset in tile
    const int wn = (wid >> 2) * 64;  // warp col offset in tile
    const int gid = lane >> 2, tig = lane & 3;

    float acc[2][8][4];
    #pragma unroll
    for (int mi = 0; mi < 2; mi++)
        #pragma unroll
        for (int ni = 0; ni < 8; ni++)
            #pragma unroll
            for (int j = 0; j < 4; j++) acc[mi][ni][j] = 0.f;

    // per-thread load coordinates (2 float4 loads each for A and B per chunk)
    int rA[2], kA[2], kB[2], nB[2];
    const float* Ap[2];
    const float* Bp[2];
    #pragma unroll
    for (int i = 0; i < 2; i++) {
        int idx = i * 256 + tid;
        rA[i] = idx >> 2;            // 0..127
        kA[i] = (idx & 3) * 4;       // 0..12
        kB[i] = idx >> 5;            // 0..15 (NN)
        nB[i] = (idx & 31) * 4;      // 0..124 (NN)
        Ap[i] = A + (long)(bm + rA[i]) * lda + kA[i];
        if (BNT == 0)
            Bp[i] = B + (long)kB[i] * ldb + bn + nB[i];
        else
            Bp[i] = B + (long)(bn + rA[i]) * ldb + kA[i];
    }

    const int nch = K / KC;
    float4 a4[2], b4[2];

    // helper lambdas via macros for fill
    #define LOAD_CHUNK(c)                                                   \
        do {                                                                \
            _Pragma("unroll")                                               \
            for (int i = 0; i < 2; i++) {                                   \
                a4[i] = *(const float4*)(Ap[i] + (long)(c) * KC);           \
                if (BNT == 0)                                               \
                    b4[i] = *(const float4*)(Bp[i] + (long)(c) * KC * ldb); \
                else                                                        \
                    b4[i] = *(const float4*)(Bp[i] + (long)(c) * KC);       \
            }                                                               \
        } while (0)

    #define FILL(buf)                                                       \
        do {                                                                \
            _Pragma("unroll")                                               \
            for (int i = 0; i < 2; i++) {                                   \
                float va[4] = {a4[i].x, a4[i].y, a4[i].z, a4[i].w};         \
                _Pragma("unroll")                                           \
                for (int j = 0; j < 4; j++) {                               \
                    __nv_bfloat16 hi, lo;                                   \
                    split_bf16(va[j], hi, lo);                              \
                    sAhi[buf][rA[i]][kA[i] + j] = hi;                       \
                    sAlo[buf][rA[i]][kA[i] + j] = lo;                       \
                }                                                           \
                float vb[4] = {b4[i].x, b4[i].y, b4[i].z, b4[i].w};         \
                _Pragma("unroll")                                           \
                for (int j = 0; j < 4; j++) {                               \
                    __nv_bfloat16 hi, lo;                                   \
                    split_bf16(vb[j], hi, lo);                              \
                    if (BNT == 0) {                                         \
                        sBhi[buf][nB[i] + j][kB[i]] = hi;                   \
                        sBlo[buf][nB[i] + j][kB[i]] = lo;                   \
                    } else {                                                \
                        sBhi[buf][rA[i]][kA[i] + j] = hi;                   \
                        sBlo[buf][rA[i]][kA[i] + j] = lo;                   \
                    }                                                       \
                }                                                           \
            }                                                               \
        } while (0)

    LOAD_CHUNK(0);
    FILL(0);
    __syncthreads();

    int cur = 0;
    for (int c = 1; c <= nch; c++) {
        bool more = (c < nch);
        if (more) LOAD_CHUNK(c);

        // ---- compute from buffer `cur` ----
        unsigned ahi[2][4], alo[2][4], bhi[8][2], blo[8][2];
        #pragma unroll
        for (int mi = 0; mi < 2; mi++) {
            int r = wm + mi * 16 + gid;
            ahi[mi][0] = *(const unsigned*)&sAhi[cur][r][2 * tig];
            ahi[mi][1] = *(const unsigned*)&sAhi[cur][r + 8][2 * tig];
            ahi[mi][2] = *(const unsigned*)&sAhi[cur][r][2 * tig + 8];
            ahi[mi][3] = *(const unsigned*)&sAhi[cur][r + 8][2 * tig + 8];
            alo[mi][0] = *(const unsigned*)&sAlo[cur][r][2 * tig];
            alo[mi][1] = *(const unsigned*)&sAlo[cur][r + 8][2 * tig];
            alo[mi][2] = *(const unsigned*)&sAlo[cur][r][2 * tig + 8];
            alo[mi][3] = *(const unsigned*)&sAlo[cur][r + 8][2 * tig + 8];
        }
        #pragma unroll
        for (int ni = 0; ni < 8; ni++) {
            int cc = wn + ni * 8 + gid;
            bhi[ni][0] = *(const unsigned*)&sBhi[cur][cc][2 * tig];
            bhi[ni][1] = *(const unsigned*)&sBhi[cur][cc][2 * tig + 8];
            blo[ni][0] = *(const unsigned*)&sBlo[cur][cc][2 * tig];
            blo[ni][1] = *(const unsigned*)&sBlo[cur][cc][2 * tig + 8];
        }
        #pragma unroll
        for (int mi = 0; mi < 2; mi++)
            #pragma unroll
            for (int ni = 0; ni < 8; ni++) {
                mma16816(acc[mi][ni], ahi[mi], bhi[ni]);
                mma16816(acc[mi][ni], ahi[mi], blo[ni]);
                mma16816(acc[mi][ni], alo[mi], bhi[ni]);
            }

        if (more) {
            int nxt = cur ^ 1;
            FILL(nxt);
            __syncthreads();
            cur = nxt;
        }
    }
    #undef LOAD_CHUNK
    #undef FILL

    // ---- epilogue ----
    const float SC = 0.0625f;  // 256^-0.5
    #pragma unroll
    for (int mi = 0; mi < 2; mi++) {
        #pragma unroll
        for (int ni = 0; ni < 8; ni++) {
            int row = bm + wm + mi * 16 + gid;
            int col = bn + wn + ni * 8 + 2 * tig;
            float* c0 = &C[(long)row * ldc + col];
            float* c1 = &C[(long)(row + 8) * ldc + col];
            float v0 = acc[mi][ni][0], v1 = acc[mi][ni][1];
            float v2 = acc[mi][ni][2], v3 = acc[mi][ni][3];
            if (EPI == 1) { v0 *= SC; v1 *= SC; v2 *= SC; v3 *= SC; }
            if (EPI == 2) {
                float2 o0 = *(const float2*)c0;
                float2 o1 = *(const float2*)c1;
                float bz0 = bias[col], bz1 = bias[col + 1];
                v0 += o0.x + bz0; v1 += o0.y + bz1;
                v2 += o1.x + bz0; v3 += o1.y + bz1;
            }
            if (EPI == 3) {
                float bz0 = bias[col], bz1 = bias[col + 1];
                v0 += bz0; v1 += bz1; v2 += bz0; v3 += bz1;
                v0 = 0.5f * v0 * (1.f + erff(v0 * 0.70710678118654752f));
                v1 = 0.5f * v1 * (1.f + erff(v1 * 0.70710678118654752f));
                v2 = 0.5f * v2 * (1.f + erff(v2 * 0.70710678118654752f));
                v3 = 0.5f * v3 * (1.f + erff(v3 * 0.70710678118654752f));
            }
            *(float2*)c0 = make_float2(v0, v1);
            *(float2*)c1 = make_float2(v2, v3);
        }
    }
}

// ---------------- kernel wrappers ----------------
template <int EPI>
__global__ void __launch_bounds__(256)
gemm_nn_tc(const float* __restrict__ A, const float* __restrict__ B,
           float* __restrict__ C, int K, int lda, int ldb, int ldc,
           const float* __restrict__ bias) {
    gemm_core<EPI, 0>(A, B, C, K, lda, ldb, ldc, bias);
}

__global__ void __launch_bounds__(256) gemm_qkt_tc() {
    int bh = blockIdx.z;
    int b = bh >> 3, h = bh & 7;
    const float* Q = g_qkv + (long)b * NSEQ * QKVC + h * DM;
    const float* Kp = Q + INNER;
    float* C = g_scores + (long)bh * NSEQ * NSEQ;
    gemm_core<1, 1>(Q, Kp, C, DM, QKVC, QKVC, NSEQ, nullptr);
}

__global__ void __launch_bounds__(256) gemm_pv_tc() {
    int bh = blockIdx.z;
    int b = bh >> 3, h = bh & 7;
    const float* P = g_scores + (long)bh * NSEQ * NSEQ;
    const float* V = g_qkv + (long)b * NSEQ * QKVC + 2 * INNER + h * DM;
    float* C = g_attnout + (long)b * NSEQ * INNER + h * DM;
    gemm_core<0, 0>(P, V, C, NSEQ, NSEQ, QKVC, INNER, nullptr);
}

// ---------------- softmax over last dim (scale already applied) ------------
__global__ void softmax_kernel() {
    long row = blockIdx.x;
    float* p = g_scores + row * NSEQ;
    int t = threadIdx.x;
    float a[4];
    #pragma unroll
    for (int i = 0; i < 4; i++) a[i] = p[t + i * 256];

    __shared__ float sh[8];
    float m = fmaxf(fmaxf(a[0], a[1]), fmaxf(a[2], a[3]));
    #pragma unroll
    for (int o = 16; o; o >>= 1) m = fmaxf(m, __shfl_xor_sync(0xffffffffu, m, o));
    if ((t & 31) == 0) sh[t >> 5] = m;
    __syncthreads();
    if (t == 0) {
        float z = sh[0];
        #pragma unroll
        for (int i = 1; i < 8; i++) z = fmaxf(z, sh[i]);
        sh[0] = z;
    }
    __syncthreads();
    m = sh[0];
    __syncthreads();

    float e[4], s = 0.f;
    #pragma unroll
    for (int i = 0; i < 4; i++) { e[i] = __expf(a[i] - m); s += e[i]; }
    #pragma unroll
    for (int o = 16; o; o >>= 1) s += __shfl_xor_sync(0xffffffffu, s, o);
    if ((t & 31) == 0) sh[t >> 5] = s;
    __syncthreads();
    if (t == 0) {
        float z = 0.f;
        #pragma unroll
        for (int i = 0; i < 8; i++) z += sh[i];
        sh[0] = z;
    }
    __syncthreads();
    float inv = 1.f / sh[0];
    #pragma unroll
    for (int i = 0; i < 4; i++) p[t + i * 256] = e[i] * inv;
}

// ---------------- host orchestration ----------------
extern "C" void kernel_launch(void* const* d_in, const int* in_sizes, int n_in,
                              void* d_out, int out_size) {
    const float* inputs = (const float*)d_in[0];
    const float* ln1_g  = (const float*)d_in[1];
    const float* ln1_b  = (const float*)d_in[2];
    const float* w_qkv  = (const float*)d_in[3];
    const float* w_proj = (const float*)d_in[4];
    const float* b_proj = (const float*)d_in[5];
    const float* ln2_g  = (const float*)d_in[6];
    const float* ln2_b  = (const float*)d_in[7];
    const float* w1     = (const float*)d_in[8];
    const float* b1     = (const float*)d_in[9];
    const float* w2     = (const float*)d_in[10];
    const float* b2     = (const float*)d_in[11];

    void *px, *ph, *pqkv, *pattn, *ph1;
    cudaGetSymbolAddress(&px, g_x);
    cudaGetSymbolAddress(&ph, g_h);
    cudaGetSymbolAddress(&pqkv, g_qkv);
    cudaGetSymbolAddress(&pattn, g_attnout);
    cudaGetSymbolAddress(&ph1, g_h1);
    float* x = (float*)px;
    float* h = (float*)ph;
    float* qkv = (float*)pqkv;
    float* attnout = (float*)pattn;
    float* h1 = (float*)ph1;

    copy_in_kernel<<<ROWS * DM / 256, 256>>>(inputs);

    for (int l = 0; l < LNUM; l++) {
        // --- attention sublayer ---
        ln_kernel<<<ROWS, 256>>>(x, ln1_g + l * DM, ln1_b + l * DM, h);
        gemm_nn_tc<0><<<dim3(QKVC / 128, ROWS / 128), 256>>>(
            h, w_qkv + (long)l * DM * QKVC, qkv, DM, DM, QKVC, QKVC, nullptr);
        gemm_qkt_tc<<<dim3(8, 8, 64), 256>>>();
        softmax_kernel<<<BSZ * HH * NSEQ, 256>>>();
        gemm_pv_tc<<<dim3(2, 8, 64), 256>>>();
        gemm_nn_tc<2><<<dim3(DM / 128, ROWS / 128), 256>>>(
            attnout, w_proj + (long)l * INNER * DM, x, INNER, INNER, DM, DM,
            b_proj + l * DM);
        // --- MLP sublayer ---
        ln_kernel<<<ROWS, 256>>>(x, ln2_g + l * DM, ln2_b + l * DM, h);
        gemm_nn_tc<3><<<dim3(MMLP / 128, ROWS / 128), 256>>>(
            h, w1 + (long)l * DM * MMLP, h1, DM, DM, MMLP, MMLP, b1 + l * MMLP);
        gemm_nn_tc<2><<<dim3(DM / 128, ROWS / 128), 256>>>(
            h1, w2 + (long)l * MMLP * DM, x, MMLP, MMLP, DM, DM, b2 + l * DM);
    }

    copy_out_kernel<<<ROWS * DM / 256, 256>>>((float*)d_out);
}

// round 10
// speedup vs baseline: 1.1606x; 1.1606x over previous
#include <cuda_runtime.h>
#include <cuda_bf16.h>
#include <math.h>

// ---------------- problem constants ----------------
#define BSZ   8
#define NSEQ  1024
#define DM    256
#define HH    8
#define INNER 2048          // H * DH, DH == DM (module quirk)
#define MMLP  1024
#define LNUM  4
#define ROWS  (BSZ * NSEQ)  // 8192
#define QKVC  (3 * INNER)   // 6144

typedef unsigned long long u64;

// ---------------- scratch (static device globals; no allocs allowed) -------
__device__ float g_x[ROWS * DM];                         // residual stream
__device__ float g_h[ROWS * DM];                         // LN output
__device__ float g_qkv[ROWS * QKVC];                     // 192 MB
__device__ float g_scores[(long)BSZ * HH * NSEQ * NSEQ]; // 256 MB
__device__ float g_attnout[ROWS * INNER];                // 64 MB
__device__ float g_h1[ROWS * MMLP];                      // 32 MB

// ---------------- copy in/out ----------------
__global__ void copy_in_kernel(const float* __restrict__ src) {
    int i = blockIdx.x * 256 + threadIdx.x;
    g_x[i] = src[i];
}
__global__ void copy_out_kernel(float* __restrict__ dst) {
    int i = blockIdx.x * 256 + threadIdx.x;
    dst[i] = g_x[i];
}

// ---------------- layernorm: one 256-thread block per row (D=256) ----------
__global__ void ln_kernel(const float* __restrict__ x,
                          const float* __restrict__ g,
                          const float* __restrict__ b,
                          float* __restrict__ out) {
    int row = blockIdx.x;
    int t = threadIdx.x;
    float v = x[row * DM + t];
    __shared__ float sh[8];

    float s = v;
    #pragma unroll
    for (int o = 16; o; o >>= 1) s += __shfl_xor_sync(0xffffffffu, s, o);
    if ((t & 31) == 0) sh[t >> 5] = s;
    __syncthreads();
    if (t == 0) {
        float z = 0.f;
        #pragma unroll
        for (int i = 0; i < 8; i++) z += sh[i];
        sh[0] = z;
    }
    __syncthreads();
    float mean = sh[0] * (1.f / 256.f);
    __syncthreads();

    float d = v - mean;
    float sq = d * d;
    #pragma unroll
    for (int o = 16; o; o >>= 1) sq += __shfl_xor_sync(0xffffffffu, sq, o);
    if ((t & 31) == 0) sh[t >> 5] = sq;
    __syncthreads();
    if (t == 0) {
        float z = 0.f;
        #pragma unroll
        for (int i = 0; i < 8; i++) z += sh[i];
        sh[0] = z;
    }
    __syncthreads();
    float var = sh[0] * (1.f / 256.f);
    float r = rsqrtf(var + 1e-5f);
    out[row * DM + t] = d * r * g[t] + b[t];
}

// ---------------- tensor-core building blocks ----------------
__device__ __forceinline__ unsigned smaddr(const void* p) {
    return (unsigned)__cvta_generic_to_shared(p);
}
__device__ __forceinline__ void ldsm4(unsigned r[4], unsigned addr) {
    asm volatile(
        "ldmatrix.sync.aligned.m8n8.x4.shared.b16 {%0,%1,%2,%3}, [%4];"
        : "=r"(r[0]), "=r"(r[1]), "=r"(r[2]), "=r"(r[3]) : "r"(addr));
}
__device__ __forceinline__ void ldsm4t(unsigned r[4], unsigned addr) {
    asm volatile(
        "ldmatrix.sync.aligned.m8n8.x4.trans.shared.b16 {%0,%1,%2,%3}, [%4];"
        : "=r"(r[0]), "=r"(r[1]), "=r"(r[2]), "=r"(r[3]) : "r"(addr));
}
__device__ __forceinline__ void mma16816(float d[4], const unsigned a[4],
                                         const unsigned b[2]) {
    asm volatile(
        "mma.sync.aligned.m16n8k16.row.col.f32.bf16.bf16.f32 "
        "{%0,%1,%2,%3}, {%4,%5,%6,%7}, {%8,%9}, {%0,%1,%2,%3};\n"
        : "+f"(d[0]), "+f"(d[1]), "+f"(d[2]), "+f"(d[3])
        : "r"(a[0]), "r"(a[1]), "r"(a[2]), "r"(a[3]), "r"(b[0]), "r"(b[1]));
}

// split fp32 -> (hi, lo) bf16 and store 4 of each as one 8-byte word
__device__ __forceinline__ void split_store4(__nv_bfloat16* hi,
                                             __nv_bfloat16* lo, float4 v) {
    float va[4] = {v.x, v.y, v.z, v.w};
    u64 uh = 0, ul = 0;
    #pragma unroll
    for (int j = 0; j < 4; j++) {
        __nv_bfloat16 h = __float2bfloat16(va[j]);
        __nv_bfloat16 l = __float2bfloat16(va[j] - __bfloat162float(h));
        uh |= (u64)__bfloat16_as_ushort(h) << (16 * j);
        ul |= (u64)__bfloat16_as_ushort(l) << (16 * j);
    }
    *(u64*)hi = uh;
    *(u64*)lo = ul;
}

// swizzled element index in a [128][16] bf16 tile (16B-chunk ^ row-bit)
__device__ __forceinline__ int aidx(int r, int k) {
    return r * 16 + ((((k >> 3) ^ ((r >> 2) & 1))) << 3) + (k & 7);
}
// swizzled element index in a [16][128] bf16 tile (n-chunk ^ k&7)
__device__ __forceinline__ int bkidx(int k, int n) {
    return k * 128 + ((((n >> 3) ^ (k & 7))) << 3) + (n & 7);
}

// ======================================================================
// Tensor-core split-bf16 GEMM core with ldmatrix + swizzled smem.
// Output tile 128x128 per CTA, 256 threads = 8 warps (4 along M x 2 along N).
// D = Ahi*Bhi + Ahi*Blo + Alo*Bhi   (fp32 accumulate, lo*lo dropped)
// BNT = 0: B is [K][N] row-major (NN), smem k-major + ldmatrix.trans.
// BNT = 1: B is [N][K] row-major (NT), smem n-major + ldmatrix.
// EPI 0: C = acc
// EPI 1: C = acc * 2^-4          (QK^T scale 1/sqrt(256))
// EPI 2: C = C + acc + bias[col] (residual accumulate, in-place)
// EPI 3: C = gelu_erf(acc + bias[col])
// ======================================================================
template <int EPI, int BNT>
__device__ __forceinline__ void gemm_core(
    const float* __restrict__ A, const float* __restrict__ B,
    float* __restrict__ C, int K, int lda, int ldb, int ldc,
    const float* __restrict__ bias) {
    __shared__ __align__(16) __nv_bfloat16 sAhi[2][2048], sAlo[2][2048];
    __shared__ __align__(16) __nv_bfloat16 sBhi[2][2048], sBlo[2][2048];

    const int bm = blockIdx.y * 128, bn = blockIdx.x * 128;
    const int tid = threadIdx.x;
    const int lane = tid & 31, wid = tid >> 5;
    const int wm = (wid & 3) * 32;   // warp row offset in tile
    const int wn = (wid >> 2) * 64;  // warp col offset in tile
    const int gid = lane >> 2, tig = lane & 3;

    float acc[2][8][4];
    #pragma unroll
    for (int mi = 0; mi < 2; mi++)
        #pragma unroll
        for (int ni = 0; ni < 8; ni++)
            #pragma unroll
            for (int j = 0; j < 4; j++) acc[mi][ni][j] = 0.f;

    // global-load coordinates + swizzled smem store offsets
    const float* Ap[2];
    const float* Bp[2];
    int aSt[2], bSt[2];
    #pragma unroll
    for (int i = 0; i < 2; i++) {
        int idx = i * 256 + tid;
        int r = idx >> 2, k = (idx & 3) * 4;     // A: row 0..127, k 0,4,8,12
        aSt[i] = aidx(r, k);
        Ap[i] = A + (long)(bm + r) * lda + k;
        if (BNT == 0) {
            int kb = idx >> 5, nb = (idx & 31) * 4;  // B: k 0..15, n 0..124
            bSt[i] = bkidx(kb, nb);
            Bp[i] = B + (long)kb * ldb + bn + nb;
        } else {
            bSt[i] = aSt[i];
            Bp[i] = B + (long)(bn + r) * ldb + k;
        }
    }

    // lane-dependent ldmatrix read offsets (element indices)
    int aRd[2];
    {
        int lr = ((lane >> 3) & 1) * 8 + (lane & 7);
        int kh = lane >> 4;
        #pragma unroll
        for (int mi = 0; mi < 2; mi++) {
            int r = wm + mi * 16 + lr;
            aRd[mi] = r * 16 + ((kh ^ ((r >> 2) & 1)) << 3);
        }
    }
    int bRd[4];
    #pragma unroll
    for (int nip = 0; nip < 4; nip++) {
        if (BNT == 0) {
            int kr = ((lane >> 3) & 1) * 8 + (lane & 7);
            int nc = ((wn + nip * 16) >> 3) + ((lane >> 4) & 1);
            bRd[nip] = kr * 128 + ((nc ^ (kr & 7)) << 3);
        } else {
            int nr = wn + nip * 16 + ((lane >> 4) & 1) * 8 + (lane & 7);
            int kh2 = (lane >> 3) & 1;
            bRd[nip] = nr * 16 + ((kh2 ^ ((nr >> 2) & 1)) << 3);
        }
    }

    const int nch = K / 16;
    float4 a4[2], b4[2];

    // prologue: chunk 0
    #pragma unroll
    for (int i = 0; i < 2; i++) {
        a4[i] = *(const float4*)Ap[i];
        b4[i] = *(const float4*)Bp[i];
    }
    #pragma unroll
    for (int i = 0; i < 2; i++) {
        split_store4(&sAhi[0][aSt[i]], &sAlo[0][aSt[i]], a4[i]);
        split_store4(&sBhi[0][bSt[i]], &sBlo[0][bSt[i]], b4[i]);
    }
    __syncthreads();

    int cur = 0;
    for (int c = 1; c <= nch; c++) {
        bool more = (c < nch);
        if (more) {
            #pragma unroll
            for (int i = 0; i < 2; i++) {
                a4[i] = *(const float4*)(Ap[i] + (long)c * 16);
                if (BNT == 0)
                    b4[i] = *(const float4*)(Bp[i] + (long)c * 16 * ldb);
                else
                    b4[i] = *(const float4*)(Bp[i] + (long)c * 16);
            }
        }

        unsigned ahi[2][4], alo[2][4];
        #pragma unroll
        for (int mi = 0; mi < 2; mi++) {
            ldsm4(ahi[mi], smaddr(&sAhi[cur][aRd[mi]]));
            ldsm4(alo[mi], smaddr(&sAlo[cur][aRd[mi]]));
        }
        #pragma unroll
        for (int nip = 0; nip < 4; nip++) {
            unsigned bhi[4], blo[4];
            if (BNT == 0) {
                ldsm4t(bhi, smaddr(&sBhi[cur][bRd[nip]]));
                ldsm4t(blo, smaddr(&sBlo[cur][bRd[nip]]));
            } else {
                ldsm4(bhi, smaddr(&sBhi[cur][bRd[nip]]));
                ldsm4(blo, smaddr(&sBlo[cur][bRd[nip]]));
            }
            #pragma unroll
            for (int mi = 0; mi < 2; mi++)
                #pragma unroll
                for (int nj = 0; nj < 2; nj++) {
                    int ni = nip * 2 + nj;
                    mma16816(acc[mi][ni], ahi[mi], &bhi[nj * 2]);
                    mma16816(acc[mi][ni], ahi[mi], &blo[nj * 2]);
                    mma16816(acc[mi][ni], alo[mi], &bhi[nj * 2]);
                }
        }

        if (more) {
            int nxt = cur ^ 1;
            #pragma unroll
            for (int i = 0; i < 2; i++) {
                split_store4(&sAhi[nxt][aSt[i]], &sAlo[nxt][aSt[i]], a4[i]);
                split_store4(&sBhi[nxt][bSt[i]], &sBlo[nxt][bSt[i]], b4[i]);
            }
            __syncthreads();
            cur = nxt;
        }
    }

    // ---- epilogue ----
    const float SC = 0.0625f;  // 256^-0.5
    #pragma unroll
    for (int mi = 0; mi < 2; mi++) {
        #pragma unroll
        for (int ni = 0; ni < 8; ni++) {
            int row = bm + wm + mi * 16 + gid;
            int col = bn + wn + ni * 8 + 2 * tig;
            float* c0 = &C[(long)row * ldc + col];
            float* c1 = &C[(long)(row + 8) * ldc + col];
            float v0 = acc[mi][ni][0], v1 = acc[mi][ni][1];
            float v2 = acc[mi][ni][2], v3 = acc[mi][ni][3];
            if (EPI == 1) { v0 *= SC; v1 *= SC; v2 *= SC; v3 *= SC; }
            if (EPI == 2) {
                float2 o0 = *(const float2*)c0;
                float2 o1 = *(const float2*)c1;
                float bz0 = bias[col], bz1 = bias[col + 1];
                v0 += o0.x + bz0; v1 += o0.y + bz1;
                v2 += o1.x + bz0; v3 += o1.y + bz1;
            }
            if (EPI == 3) {
                float bz0 = bias[col], bz1 = bias[col + 1];
                v0 += bz0; v1 += bz1; v2 += bz0; v3 += bz1;
                v0 = 0.5f * v0 * (1.f + erff(v0 * 0.70710678118654752f));
                v1 = 0.5f * v1 * (1.f + erff(v1 * 0.70710678118654752f));
                v2 = 0.5f * v2 * (1.f + erff(v2 * 0.70710678118654752f));
                v3 = 0.5f * v3 * (1.f + erff(v3 * 0.70710678118654752f));
            }
            *(float2*)c0 = make_float2(v0, v1);
            *(float2*)c1 = make_float2(v2, v3);
        }
    }
}

// ---------------- kernel wrappers ----------------
template <int EPI>
__global__ void __launch_bounds__(256, 2)
gemm_nn_tc(const float* __restrict__ A, const float* __restrict__ B,
           float* __restrict__ C, int K, int lda, int ldb, int ldc,
           const float* __restrict__ bias) {
    gemm_core<EPI, 0>(A, B, C, K, lda, ldb, ldc, bias);
}

__global__ void __launch_bounds__(256, 2) gemm_qkt_tc() {
    int bh = blockIdx.z;
    int b = bh >> 3, h = bh & 7;
    const float* Q = g_qkv + (long)b * NSEQ * QKVC + h * DM;
    const float* Kp = Q + INNER;
    float* C = g_scores + (long)bh * NSEQ * NSEQ;
    gemm_core<1, 1>(Q, Kp, C, DM, QKVC, QKVC, NSEQ, nullptr);
}

__global__ void __launch_bounds__(256, 2) gemm_pv_tc() {
    int bh = blockIdx.z;
    int b = bh >> 3, h = bh & 7;
    const float* P = g_scores + (long)bh * NSEQ * NSEQ;
    const float* V = g_qkv + (long)b * NSEQ * QKVC + 2 * INNER + h * DM;
    float* C = g_attnout + (long)b * NSEQ * INNER + h * DM;
    gemm_core<0, 0>(P, V, C, NSEQ, NSEQ, QKVC, INNER, nullptr);
}

// ---------------- softmax over last dim (scale already applied) ------------
__global__ void softmax_kernel() {
    long row = blockIdx.x;
    float* p = g_scores + row * NSEQ;
    int t = threadIdx.x;
    float a[4];
    #pragma unroll
    for (int i = 0; i < 4; i++) a[i] = p[t + i * 256];

    __shared__ float sh[8];
    float m = fmaxf(fmaxf(a[0], a[1]), fmaxf(a[2], a[3]));
    #pragma unroll
    for (int o = 16; o; o >>= 1) m = fmaxf(m, __shfl_xor_sync(0xffffffffu, m, o));
    if ((t & 31) == 0) sh[t >> 5] = m;
    __syncthreads();
    if (t == 0) {
        float z = sh[0];
        #pragma unroll
        for (int i = 1; i < 8; i++) z = fmaxf(z, sh[i]);
        sh[0] = z;
    }
    __syncthreads();
    m = sh[0];
    __syncthreads();

    float e[4], s = 0.f;
    #pragma unroll
    for (int i = 0; i < 4; i++) { e[i] = __expf(a[i] - m); s += e[i]; }
    #pragma unroll
    for (int o = 16; o; o >>= 1) s += __shfl_xor_sync(0xffffffffu, s, o);
    if ((t & 31) == 0) sh[t >> 5] = s;
    __syncthreads();
    if (t == 0) {
        float z = 0.f;
        #pragma unroll
        for (int i = 0; i < 8; i++) z += sh[i];
        sh[0] = z;
    }
    __syncthreads();
    float inv = 1.f / sh[0];
    #pragma unroll
    for (int i = 0; i < 4; i++) p[t + i * 256] = e[i] * inv;
}

// ---------------- host orchestration ----------------
extern "C" void kernel_launch(void* const* d_in, const int* in_sizes, int n_in,
                              void* d_out, int out_size) {
    const float* inputs = (const float*)d_in[0];
    const float* ln1_g  = (const float*)d_in[1];
    const float* ln1_b  = (const float*)d_in[2];
    const float* w_qkv  = (const float*)d_in[3];
    const float* w_proj = (const float*)d_in[4];
    const float* b_proj = (const float*)d_in[5];
    const float* ln2_g  = (const float*)d_in[6];
    const float* ln2_b  = (const float*)d_in[7];
    const float* w1     = (const float*)d_in[8];
    const float* b1     = (const float*)d_in[9];
    const float* w2     = (const float*)d_in[10];
    const float* b2     = (const float*)d_in[11];

    void *px, *ph, *pqkv, *pattn, *ph1;
    cudaGetSymbolAddress(&px, g_x);
    cudaGetSymbolAddress(&ph, g_h);
    cudaGetSymbolAddress(&pqkv, g_qkv);
    cudaGetSymbolAddress(&pattn, g_attnout);
    cudaGetSymbolAddress(&ph1, g_h1);
    float* x = (float*)px;
    float* h = (float*)ph;
    float* qkv = (float*)pqkv;
    float* attnout = (float*)pattn;
    float* h1 = (float*)ph1;

    copy_in_kernel<<<ROWS * DM / 256, 256>>>(inputs);

    for (int l = 0; l < LNUM; l++) {
        // --- attention sublayer ---
        ln_kernel<<<ROWS, 256>>>(x, ln1_g + l * DM, ln1_b + l * DM, h);
        gemm_nn_tc<0><<<dim3(QKVC / 128, ROWS / 128), 256>>>(
            h, w_qkv + (long)l * DM * QKVC, qkv, DM, DM, QKVC, QKVC, nullptr);
        gemm_qkt_tc<<<dim3(8, 8, 64), 256>>>();
        softmax_kernel<<<BSZ * HH * NSEQ, 256>>>();
        gemm_pv_tc<<<dim3(2, 8, 64), 256>>>();
        gemm_nn_tc<2><<<dim3(DM / 128, ROWS / 128), 256>>>(
            attnout, w_proj + (long)l * INNER * DM, x, INNER, INNER, DM, DM,
            b_proj + l * DM);
        // --- MLP sublayer ---
        ln_kernel<<<ROWS, 256>>>(x, ln2_g + l * DM, ln2_b + l * DM, h);
        gemm_nn_tc<3><<<dim3(MMLP / 128, ROWS / 128), 256>>>(
            h, w1 + (long)l * DM * MMLP, h1, DM, DM, MMLP, MMLP, b1 + l * MMLP);
        gemm_nn_tc<2><<<dim3(DM / 128, ROWS / 128), 256>>>(
            h1, w2 + (long)l * MMLP * DM, x, MMLP, MMLP, DM, DM, b2 + l * DM);
    }

    copy_out_kernel<<<ROWS * DM / 256, 256>>>((float*)d_out);
}